// round 3
// baseline (speedup 1.0000x reference)
#include <cuda_runtime.h>
#include <math.h>

// Problem constants
#define NN 10000      // nodes
#define NE 160000     // edges
#define FIN 4         // input features
#define HID 32        // hidden
#define NC 4          // classes
#define ED 2          // edge attr dim

// Scratch (module-static device globals: allowed; no runtime allocation)
__device__ float g_G[NN * HID * HID];   // [n, j, o]  40.96 MB  (L2-resident)
__device__ float g_B[NN * HID];         // per-src b2 term
__device__ float g_agg[NN * HID];       // accumulator, pre-initialized with x@root+bias
__device__ float g_x[NN * HID];         // node features between layers

// ---------------------------------------------------------------------------
// kA: G[n, j*32+o] = sum_i x[n,i] * w2[j*(DIN*32) + i*32 + o]
// 8 nodes per 256-thread block; each thread owns 4 output columns x 8 nodes.
// w2 read once per block (amortized over 8 nodes) -> L1-resident across blocks.
// ---------------------------------------------------------------------------
template<int DIN, bool USE_GX>
__global__ __launch_bounds__(256) void kA(const float* __restrict__ xin,
                                          const float* __restrict__ w2) {
    const float* xp = USE_GX ? g_x : xin;
    __shared__ float xs[8][DIN];
    const int base = blockIdx.x * 8;
    const int tid = threadIdx.x;

    for (int idx = tid; idx < 8 * DIN; idx += 256) {
        int m = idx / DIN, i = idx % DIN;
        int n = base + m;
        xs[m][i] = (n < NN) ? xp[n * DIN + i] : 0.f;
    }
    __syncthreads();

    float acc[8][4];
#pragma unroll
    for (int m = 0; m < 8; m++)
#pragma unroll
        for (int k = 0; k < 4; k++) acc[m][k] = 0.f;

#pragma unroll 4
    for (int i = 0; i < DIN; i++) {
        float wv[4];
#pragma unroll
        for (int k = 0; k < 4; k++) {
            int col = tid + 256 * k;                 // col = j*32 + o
            wv[k] = w2[(col >> 5) * (DIN * 32) + i * 32 + (col & 31)];
        }
#pragma unroll
        for (int m = 0; m < 8; m++) {
            float xv = xs[m][i];
#pragma unroll
            for (int k = 0; k < 4; k++) acc[m][k] = fmaf(xv, wv[k], acc[m][k]);
        }
    }

#pragma unroll
    for (int m = 0; m < 8; m++) {
        int n = base + m;
        if (n < NN) {
#pragma unroll
            for (int k = 0; k < 4; k++)
                g_G[n * 1024 + tid + 256 * k] = acc[m][k];
        }
    }
}

// ---------------------------------------------------------------------------
// kA2: B[n,o] = sum_i x[n,i]*b2[i*32+o]
//      agg[n,o] = bias[o] + sum_i x[n,i]*root[i*32+o]   (NNConv root term,
//      pre-seeded so the edge kernel only needs atomic adds)
// ---------------------------------------------------------------------------
template<int DIN, bool USE_GX>
__global__ __launch_bounds__(256) void kA2(const float* __restrict__ xin,
                                           const float* __restrict__ b2,
                                           const float* __restrict__ root,
                                           const float* __restrict__ bias) {
    const float* xp = USE_GX ? g_x : xin;
    int t = blockIdx.x * 256 + threadIdx.x;
    if (t >= NN * HID) return;
    int n = t >> 5, o = t & 31;
    float b = 0.f;
    float a = bias[o];
#pragma unroll 4
    for (int i = 0; i < DIN; i++) {
        float xv = xp[n * DIN + i];
        b = fmaf(xv, b2[i * 32 + o], b);
        a = fmaf(xv, root[i * 32 + o], a);
    }
    g_B[t] = b;
    g_agg[t] = a;
}

// ---------------------------------------------------------------------------
// kB: one warp per edge, lane = output channel o.
//   h[j]   = relu(ea0*w1[0,j] + ea1*w1[1,j] + b1[j])          (lane j computes)
//   msg[o] = B[src,o] + sum_j h[j] * G[src, j, o]             (shfl-broadcast h)
//   atomicAdd(agg[dst,o], msg[o])  -> REDG (return unused)
// G row reads are 128B-coalesced per j; 4 KB per edge, all L2 hits (G = 40 MB).
// ---------------------------------------------------------------------------
__global__ __launch_bounds__(256) void kB(const int* __restrict__ ei,
                                          const float* __restrict__ ea,
                                          const float* __restrict__ w1,
                                          const float* __restrict__ b1) {
    int warp = (blockIdx.x * 256 + threadIdx.x) >> 5;
    int lane = threadIdx.x & 31;
    if (warp >= NE) return;
    int e = warp;
    int src = ei[e];
    int dst = ei[NE + e];
    float a0 = ea[2 * e];
    float a1 = ea[2 * e + 1];
    float h = fmaxf(fmaf(a0, w1[lane], fmaf(a1, w1[32 + lane], b1[lane])), 0.f);

    const float* __restrict__ Gs = g_G + (size_t)src * 1024;
    float acc = g_B[src * 32 + lane];
#pragma unroll
    for (int j = 0; j < 32; j++) {
        float hj = __shfl_sync(0xffffffffu, h, j);
        acc = fmaf(hj, Gs[j * 32 + lane], acc);
    }
    atomicAdd(&g_agg[dst * 32 + lane], acc);
}

// ---------------------------------------------------------------------------
// kC: relu(agg) -> g_x
// ---------------------------------------------------------------------------
__global__ __launch_bounds__(256) void kC() {
    int t = blockIdx.x * 256 + threadIdx.x;
    if (t < NN * HID) g_x[t] = fmaxf(g_agg[t], 0.f);
}

// ---------------------------------------------------------------------------
// kF: logits = x @ fc_w + fc_b ; out = log_softmax(logits)
// ---------------------------------------------------------------------------
__global__ __launch_bounds__(256) void kF(const float* __restrict__ fcw,
                                          const float* __restrict__ fcb,
                                          float* __restrict__ out) {
    int n = blockIdx.x * 256 + threadIdx.x;
    if (n >= NN) return;
    float l[NC];
#pragma unroll
    for (int c = 0; c < NC; c++) l[c] = fcb[c];
    const float4* xr = reinterpret_cast<const float4*>(g_x) + n * 8;
#pragma unroll
    for (int q = 0; q < 8; q++) {
        float4 v = xr[q];
        float xv[4] = {v.x, v.y, v.z, v.w};
#pragma unroll
        for (int s = 0; s < 4; s++) {
            int o = q * 4 + s;
#pragma unroll
            for (int c = 0; c < NC; c++) l[c] = fmaf(xv[s], fcw[o * NC + c], l[c]);
        }
    }
    float m = l[0];
#pragma unroll
    for (int c = 1; c < NC; c++) m = fmaxf(m, l[c]);
    float s = 0.f;
#pragma unroll
    for (int c = 0; c < NC; c++) s += expf(l[c] - m);
    float lse = m + logf(s);
#pragma unroll
    for (int c = 0; c < NC; c++) out[n * NC + c] = l[c] - lse;
}

// ---------------------------------------------------------------------------
extern "C" void kernel_launch(void* const* d_in, const int* in_sizes, int n_in,
                              void* d_out, int out_size) {
    const float* x   = (const float*)d_in[0];   // [N, 4]
    const int*   ei  = (const int*)d_in[1];     // [2, E]
    const float* ea  = (const float*)d_in[2];   // [E, 2]
    const float *W1[3], *B1[3], *W2[3], *B2[3], *RT[3], *BI[3];
    for (int l = 0; l < 3; l++) {
        W1[l] = (const float*)d_in[3 + 6 * l + 0];
        B1[l] = (const float*)d_in[3 + 6 * l + 1];
        W2[l] = (const float*)d_in[3 + 6 * l + 2];
        B2[l] = (const float*)d_in[3 + 6 * l + 3];
        RT[l] = (const float*)d_in[3 + 6 * l + 4];
        BI[l] = (const float*)d_in[3 + 6 * l + 5];
    }
    const float* fcw = (const float*)d_in[21];
    const float* fcb = (const float*)d_in[22];
    float* out = (float*)d_out;

    const int gA  = (NN + 7) / 8;               // 1250
    const int gA2 = (NN * HID + 255) / 256;     // 1250
    const int gB  = NE / 8;                     // 20000 blocks x 8 warps
    const int gC  = (NN * HID + 255) / 256;
    const int gF  = (NN + 255) / 256;

    // ---- layer 0 (din = 4, input = d_in[0]) ----
    kA <FIN, false><<<gA, 256>>>(x, W2[0]);
    kA2<FIN, false><<<gA2, 256>>>(x, B2[0], RT[0], BI[0]);
    kB<<<gB, 256>>>(ei, ea, W1[0], B1[0]);
    kC<<<gC, 256>>>();

    // ---- layer 1 (din = 32, input = g_x) ----
    kA <HID, true><<<gA, 256>>>(nullptr, W2[1]);
    kA2<HID, true><<<gA2, 256>>>(nullptr, B2[1], RT[1], BI[1]);
    kB<<<gB, 256>>>(ei, ea, W1[1], B1[1]);
    kC<<<gC, 256>>>();

    // ---- layer 2 (din = 32, input = g_x) ----
    kA <HID, true><<<gA, 256>>>(nullptr, W2[2]);
    kA2<HID, true><<<gA2, 256>>>(nullptr, B2[2], RT[2], BI[2]);
    kB<<<gB, 256>>>(ei, ea, W1[2], B1[2]);
    kC<<<gC, 256>>>();

    // ---- classifier + log_softmax ----
    kF<<<gF, 256>>>(fcw, fcb, out);
}

// round 5
// speedup vs baseline: 1.6005x; 1.6005x over previous
#include <cuda_runtime.h>
#include <math.h>

// Problem constants
#define NN 10000      // nodes
#define NE 160000     // edges
#define FIN 4         // input features
#define HID 32        // hidden
#define NC 4          // classes

// ---------------- device scratch (static globals: allowed) ----------------
__device__ float g_G[NN * HID * HID];    // [n, j, o]  40.96 MB (L2-resident)
__device__ float g_B[NN * HID];          // per-src b2 term
__device__ float g_agg[2][NN * HID];     // ping-pong accumulators
// edge sort-by-src structures
__device__ int    g_deg[NN];
__device__ int    g_start[NN + 1];
__device__ int    g_cur[NN];
__device__ int    g_sdst[NE];
__device__ float2 g_sea[NE];

// ---------------------------------------------------------------------------
// Edge counting sort (runs once per launch; edges shared by all 3 layers)
// ---------------------------------------------------------------------------
__global__ __launch_bounds__(256) void k_zero() {
    int t = blockIdx.x * 256 + threadIdx.x;
    if (t < NN) g_deg[t] = 0;
}

__global__ __launch_bounds__(256) void k_hist(const int* __restrict__ ei) {
    int e = blockIdx.x * 256 + threadIdx.x;
    if (e < NE) atomicAdd(&g_deg[ei[e]], 1);
}

// single-block exclusive scan over NN bins
__global__ __launch_bounds__(256) void k_scan() {
    __shared__ int part[256];
    const int PER = (NN + 255) / 256;   // 40
    int tid = threadIdx.x;
    int base = tid * PER;
    int s = 0;
    for (int k = 0; k < PER; k++) {
        int i = base + k;
        if (i < NN) s += g_deg[i];
    }
    part[tid] = s;
    __syncthreads();
    // inclusive Hillis-Steele scan
    for (int off = 1; off < 256; off <<= 1) {
        int v = (tid >= off) ? part[tid - off] : 0;
        __syncthreads();
        part[tid] += v;
        __syncthreads();
    }
    int run = tid ? part[tid - 1] : 0;
    for (int k = 0; k < PER; k++) {
        int i = base + k;
        if (i < NN) {
            g_start[i] = run;
            g_cur[i] = run;
            run += g_deg[i];
        }
    }
    if (tid == 255) g_start[NN] = part[255];
}

__global__ __launch_bounds__(256) void k_scatter(const int* __restrict__ ei,
                                                 const float* __restrict__ ea) {
    int e = blockIdx.x * 256 + threadIdx.x;
    if (e >= NE) return;
    int src = ei[e];
    int pos = atomicAdd(&g_cur[src], 1);
    g_sdst[pos] = ei[NE + e];
    g_sea[pos] = make_float2(ea[2 * e], ea[2 * e + 1]);
}

// ---------------------------------------------------------------------------
// kA: G[n, j*32+o] = sum_i x[n,i] * w2[j*(DIN*32) + i*32 + o]
// 8 nodes / 256-thread block; w2 reads amortized across the 8 nodes.
// MODE 0: external x (no relu).  MODE 1: g_agg[rd] with relu-on-read.
// ---------------------------------------------------------------------------
template<int DIN, int MODE>
__global__ __launch_bounds__(256) void kA(const float* __restrict__ xext,
                                          const float* __restrict__ w2, int rd) {
    __shared__ float xs[8][DIN];
    const int base = blockIdx.x * 8;
    const int tid = threadIdx.x;

    for (int idx = tid; idx < 8 * DIN; idx += 256) {
        int m = idx / DIN, i = idx % DIN;
        int n = base + m;
        float v = 0.f;
        if (n < NN)
            v = MODE ? fmaxf(g_agg[rd][n * DIN + i], 0.f) : xext[n * DIN + i];
        xs[m][i] = v;
    }
    __syncthreads();

    float acc[8][4];
#pragma unroll
    for (int m = 0; m < 8; m++)
#pragma unroll
        for (int k = 0; k < 4; k++) acc[m][k] = 0.f;

#pragma unroll 4
    for (int i = 0; i < DIN; i++) {
        float wv[4];
#pragma unroll
        for (int k = 0; k < 4; k++) {
            int col = tid + 256 * k;                  // col = j*32 + o
            wv[k] = w2[(col >> 5) * (DIN * 32) + i * 32 + (col & 31)];
        }
#pragma unroll
        for (int m = 0; m < 8; m++) {
            float xv = xs[m][i];
#pragma unroll
            for (int k = 0; k < 4; k++) acc[m][k] = fmaf(xv, wv[k], acc[m][k]);
        }
    }

#pragma unroll
    for (int m = 0; m < 8; m++) {
        int n = base + m;
        if (n < NN) {
#pragma unroll
            for (int k = 0; k < 4; k++)
                g_G[(size_t)n * 1024 + tid + 256 * k] = acc[m][k];
        }
    }
}

// ---------------------------------------------------------------------------
// kA2: B[n,o] = sum_i x[n,i]*b2[i*32+o]
//      agg[wr][n,o] = bias[o] + sum_i x[n,i]*root[i*32+o]
// ---------------------------------------------------------------------------
template<int DIN, int MODE>
__global__ __launch_bounds__(256) void kA2(const float* __restrict__ xext,
                                           const float* __restrict__ b2,
                                           const float* __restrict__ root,
                                           const float* __restrict__ bias,
                                           int rd, int wr) {
    int t = blockIdx.x * 256 + threadIdx.x;
    if (t >= NN * HID) return;
    int n = t >> 5, o = t & 31;
    float b = 0.f;
    float a = bias[o];
#pragma unroll 4
    for (int i = 0; i < DIN; i++) {
        float xv = MODE ? fmaxf(g_agg[rd][n * DIN + i], 0.f) : xext[n * DIN + i];
        b = fmaf(xv, b2[i * 32 + o], b);
        a = fmaf(xv, root[i * 32 + o], a);
    }
    g_B[t] = b;
    g_agg[wr][t] = a;
}

// ---------------------------------------------------------------------------
// kB2: one warp per SOURCE node (edges pre-sorted by src).
//  - warp loads G[n] into 32 regs once (32 coalesced 128B loads)
//  - per edge: h_j on lane j (3 FMA), msg[o] = B + sum_j shfl(h,j)*G[j] (o=lane)
//  - 128B-coalesced atomicAdd scatter to agg[wr][dst]
// G traffic: 40MB/layer total (was 640MB with per-edge gather).
// ---------------------------------------------------------------------------
__global__ __launch_bounds__(256) void kB2(const float* __restrict__ w1,
                                           const float* __restrict__ b1, int wr) {
    int n = (blockIdx.x * 256 + threadIdx.x) >> 5;
    int lane = threadIdx.x & 31;
    if (n >= NN) return;
    int beg = g_start[n], end = g_start[n + 1];
    if (beg == end) return;

    float w10 = w1[lane], w11 = w1[32 + lane], b1v = b1[lane];
    const float* __restrict__ Gs = g_G + (size_t)n * 1024;
    float Gr[32];
#pragma unroll
    for (int j = 0; j < 32; j++) Gr[j] = Gs[j * 32 + lane];
    float Bv = g_B[n * 32 + lane];

    for (int e = beg; e < end; e++) {
        float2 a = g_sea[e];
        int dst = g_sdst[e];
        float h = fmaxf(fmaf(a.x, w10, fmaf(a.y, w11, b1v)), 0.f);
        float acc = Bv;
#pragma unroll
        for (int j = 0; j < 32; j++)
            acc = fmaf(__shfl_sync(0xffffffffu, h, j), Gr[j], acc);
        atomicAdd(&g_agg[wr][dst * 32 + lane], acc);
    }
}

// ---------------------------------------------------------------------------
// kF: relu -> logits = x @ fc_w + fc_b -> log_softmax
// ---------------------------------------------------------------------------
__global__ __launch_bounds__(256) void kF(const float* __restrict__ fcw,
                                          const float* __restrict__ fcb,
                                          float* __restrict__ out, int rd) {
    int n = blockIdx.x * 256 + threadIdx.x;
    if (n >= NN) return;
    float l[NC];
#pragma unroll
    for (int c = 0; c < NC; c++) l[c] = fcb[c];
    const float4* xr = reinterpret_cast<const float4*>(g_agg[rd]) + n * 8;
#pragma unroll
    for (int q = 0; q < 8; q++) {
        float4 v = xr[q];
        float xv[4] = {fmaxf(v.x, 0.f), fmaxf(v.y, 0.f), fmaxf(v.z, 0.f), fmaxf(v.w, 0.f)};
#pragma unroll
        for (int s = 0; s < 4; s++) {
            int o = q * 4 + s;
#pragma unroll
            for (int c = 0; c < NC; c++) l[c] = fmaf(xv[s], fcw[o * NC + c], l[c]);
        }
    }
    float m = l[0];
#pragma unroll
    for (int c = 1; c < NC; c++) m = fmaxf(m, l[c]);
    float s = 0.f;
#pragma unroll
    for (int c = 0; c < NC; c++) s += expf(l[c] - m);
    float lse = m + logf(s);
#pragma unroll
    for (int c = 0; c < NC; c++) out[n * NC + c] = l[c] - lse;
}

// ---------------------------------------------------------------------------
extern "C" void kernel_launch(void* const* d_in, const int* in_sizes, int n_in,
                              void* d_out, int out_size) {
    const float* x   = (const float*)d_in[0];   // [N, 4]
    const int*   ei  = (const int*)d_in[1];     // [2, E]
    const float* ea  = (const float*)d_in[2];   // [E, 2]
    const float *W1[3], *B1[3], *W2[3], *B2[3], *RT[3], *BI[3];
    for (int l = 0; l < 3; l++) {
        W1[l] = (const float*)d_in[3 + 6 * l + 0];
        B1[l] = (const float*)d_in[3 + 6 * l + 1];
        W2[l] = (const float*)d_in[3 + 6 * l + 2];
        B2[l] = (const float*)d_in[3 + 6 * l + 3];
        RT[l] = (const float*)d_in[3 + 6 * l + 4];
        BI[l] = (const float*)d_in[3 + 6 * l + 5];
    }
    const float* fcw = (const float*)d_in[21];
    const float* fcb = (const float*)d_in[22];
    float* out = (float*)d_out;

    const int gA  = (NN + 7) / 8;               // 1250
    const int gA2 = (NN * HID + 255) / 256;     // 1250
    const int gE  = (NE + 255) / 256;           // 625
    const int gB  = (NN * 32 + 255) / 256;      // 1250 (one warp per node)
    const int gF  = (NN + 255) / 256;
    const int gZ  = (NN + 255) / 256;

    // ---- sort edges by src (once; shared by all layers) ----
    k_zero<<<gZ, 256>>>();
    k_hist<<<gE, 256>>>(ei);
    k_scan<<<1, 256>>>();
    k_scatter<<<gE, 256>>>(ei, ea);

    // ---- layer 0 (din=4, external input, write agg[0]) ----
    kA <FIN, 0><<<gA, 256>>>(x, W2[0], 0);
    kA2<FIN, 0><<<gA2, 256>>>(x, B2[0], RT[0], BI[0], 0, 0);
    kB2<<<gB, 256>>>(W1[0], B1[0], 0);

    // ---- layer 1 (din=32, read agg[0] w/ relu, write agg[1]) ----
    kA <HID, 1><<<gA, 256>>>(nullptr, W2[1], 0);
    kA2<HID, 1><<<gA2, 256>>>(nullptr, B2[1], RT[1], BI[1], 0, 1);
    kB2<<<gB, 256>>>(W1[1], B1[1], 1);

    // ---- layer 2 (din=32, read agg[1] w/ relu, write agg[0]) ----
    kA <HID, 1><<<gA, 256>>>(nullptr, W2[2], 1);
    kA2<HID, 1><<<gA2, 256>>>(nullptr, B2[2], RT[2], BI[2], 1, 0);
    kB2<<<gB, 256>>>(W1[2], B1[2], 0);

    // ---- classifier + log_softmax (relu on read) ----
    kF<<<gF, 256>>>(fcw, fcb, out, 0);
}

// round 6
// speedup vs baseline: 1.8843x; 1.1773x over previous
#include <cuda_runtime.h>
#include <math.h>

// Problem constants
#define NN 10000      // nodes
#define NE 160000     // edges
#define FIN 4         // input features
#define HID 32        // hidden
#define NC 4          // classes
#define EB 16         // edges per smem batch in kB3

typedef unsigned long long ull;

// ---- packed fp32x2 helpers (sm_103a) ----
#define FMA2(d, a, b, c) \
    asm("fma.rn.f32x2 %0, %1, %2, %3;" : "=l"(d) : "l"(a), "l"(b), "l"(c))
#define PACK2(d, lo, hi) \
    asm("mov.b64 %0, {%1, %2};" : "=l"(d) : "r"(__float_as_uint(lo)), "r"(__float_as_uint(hi)))
#define UNPACK2(lo, hi, v) do { unsigned _ul, _uh;                        \
    asm("mov.b64 {%0, %1}, %2;" : "=r"(_ul), "=r"(_uh) : "l"(v));          \
    lo = __uint_as_float(_ul); hi = __uint_as_float(_uh); } while (0)

// ---------------- device scratch (static globals: allowed) ----------------
__device__ float g_G[NN * HID * HID];    // [n, j, o]  40.96 MB (L2-resident)
__device__ float g_B[NN * HID];          // per-src b2 term
__device__ float g_agg[2][NN * HID];     // ping-pong accumulators
// edge sort-by-src structures
__device__ int    g_deg[NN];
__device__ int    g_start[NN + 1];
__device__ int    g_cur[NN];
__device__ int    g_sdst[NE];
__device__ float2 g_sea[NE];

// ---------------------------------------------------------------------------
// Edge counting sort (once per launch; edges shared by all 3 layers)
// ---------------------------------------------------------------------------
__global__ __launch_bounds__(256) void k_zero() {
    int t = blockIdx.x * 256 + threadIdx.x;
    if (t < NN) g_deg[t] = 0;
}

__global__ __launch_bounds__(256) void k_hist(const int* __restrict__ ei) {
    int e = blockIdx.x * 256 + threadIdx.x;
    if (e < NE) atomicAdd(&g_deg[ei[e]], 1);
}

__global__ __launch_bounds__(256) void k_scan() {
    __shared__ int part[256];
    const int PER = (NN + 255) / 256;   // 40
    int tid = threadIdx.x;
    int base = tid * PER;
    int s = 0;
    for (int k = 0; k < PER; k++) {
        int i = base + k;
        if (i < NN) s += g_deg[i];
    }
    part[tid] = s;
    __syncthreads();
    for (int off = 1; off < 256; off <<= 1) {
        int v = (tid >= off) ? part[tid - off] : 0;
        __syncthreads();
        part[tid] += v;
        __syncthreads();
    }
    int run = tid ? part[tid - 1] : 0;
    for (int k = 0; k < PER; k++) {
        int i = base + k;
        if (i < NN) {
            g_start[i] = run;
            g_cur[i] = run;
            run += g_deg[i];
        }
    }
    if (tid == 255) g_start[NN] = part[255];
}

__global__ __launch_bounds__(256) void k_scatter(const int* __restrict__ ei,
                                                 const float* __restrict__ ea) {
    int e = blockIdx.x * 256 + threadIdx.x;
    if (e >= NE) return;
    int src = ei[e];
    int pos = atomicAdd(&g_cur[src], 1);
    g_sdst[pos] = ei[NE + e];
    g_sea[pos] = make_float2(ea[2 * e], ea[2 * e + 1]);
}

// ---------------------------------------------------------------------------
// kAF: fused G-GEMM + B + agg-init.  16 nodes per 256-thread block.
//   G[n, j*32+o] = sum_i x[n,i] * w2[j*(DIN*32) + i*32 + o]
//   B[n,o]      = sum_i x[n,i] * b2[i*32+o]
//   agg[wr][n,o]= bias[o] + sum_i x[n,i]*root[i*32+o]
// Main loop packs node-pairs into f32x2 FFMAs (halves fma-pipe issue).
// MODE 0: external x.  MODE 1: g_agg[rd] with relu-on-read.
// Grid 625 * 16 = 10000 nodes exactly (no bounds checks).
// ---------------------------------------------------------------------------
template<int DIN, int MODE>
__global__ __launch_bounds__(256) void kAF(const float* __restrict__ xext,
                                           const float* __restrict__ w2,
                                           const float* __restrict__ b2,
                                           const float* __restrict__ root,
                                           const float* __restrict__ bias,
                                           int rd, int wr) {
    __shared__ float xs[16][DIN];
    const int base = blockIdx.x * 16;
    const int tid = threadIdx.x;

    for (int idx = tid; idx < 16 * DIN; idx += 256) {
        int m = idx / DIN, i = idx % DIN;
        int n = base + m;
        xs[m][i] = MODE ? fmaxf(g_agg[rd][n * DIN + i], 0.f)
                        : xext[n * DIN + i];
    }
    __syncthreads();

    ull acc2[8][4];
#pragma unroll
    for (int p = 0; p < 8; p++)
#pragma unroll
        for (int k = 0; k < 4; k++) PACK2(acc2[p][k], 0.f, 0.f);

#pragma unroll 4
    for (int i = 0; i < DIN; i++) {
        ull wp[4];
#pragma unroll
        for (int k = 0; k < 4; k++) {
            int col = tid + 256 * k;                  // col = j*32 + o
            float wv = w2[(col >> 5) * (DIN * 32) + i * 32 + (col & 31)];
            PACK2(wp[k], wv, wv);
        }
#pragma unroll
        for (int p = 0; p < 8; p++) {
            ull x2;
            PACK2(x2, xs[2 * p][i], xs[2 * p + 1][i]);
#pragma unroll
            for (int k = 0; k < 4; k++) FMA2(acc2[p][k], x2, wp[k], acc2[p][k]);
        }
    }

#pragma unroll
    for (int p = 0; p < 8; p++) {
        int n0 = base + 2 * p;
#pragma unroll
        for (int k = 0; k < 4; k++) {
            float v0, v1;
            UNPACK2(v0, v1, acc2[p][k]);
            g_G[(size_t)n0 * 1024 + tid + 256 * k]       = v0;
            g_G[(size_t)(n0 + 1) * 1024 + tid + 256 * k] = v1;
        }
    }

    // --- B + agg-init: 512 (m,o) pairs over 256 threads ---
#pragma unroll
    for (int t = tid; t < 512; t += 256) {
        int m = t >> 5, o = t & 31;
        float b = 0.f;
        float a = bias[o];
#pragma unroll 4
        for (int i = 0; i < DIN; i++) {
            float xv = xs[m][i];
            b = fmaf(xv, b2[i * 32 + o], b);
            a = fmaf(xv, root[i * 32 + o], a);
        }
        int n = base + m;
        g_B[n * 32 + o] = b;
        g_agg[wr][n * 32 + o] = a;
    }
}

// ---------------------------------------------------------------------------
// kB3: one warp per SOURCE node (edges pre-sorted by src).
//  - warp loads G[n] once into 16 packed f32x2 register pairs per lane
//  - h staged through smem: 1 STS/edge, 8 LDS.128 broadcast reads cover 32 j
//  - contraction = 16 FFMA2/edge across 2 independent packed accumulators
//  - 128B-coalesced REDG scatter to agg[wr][dst]
// ---------------------------------------------------------------------------
__global__ __launch_bounds__(256) void kB3(const float* __restrict__ w1,
                                           const float* __restrict__ b1, int wr) {
    __shared__ __align__(16) float hs[8][EB][32];
    const int w = threadIdx.x >> 5;
    const int lane = threadIdx.x & 31;
    const int n = blockIdx.x * 8 + w;
    const int beg = g_start[n], end = g_start[n + 1];
    if (beg == end) return;

    const float w10 = w1[lane], w11 = w1[32 + lane], b1v = b1[lane];
    const float* __restrict__ Gs = g_G + (size_t)n * 1024;

    ull G2[16];
#pragma unroll
    for (int q = 0; q < 16; q++) {
        float g0 = Gs[(2 * q) * 32 + lane];
        float g1 = Gs[(2 * q + 1) * 32 + lane];
        PACK2(G2[q], g0, g1);
    }
    float Bv = g_B[n * 32 + lane];
    ull accInit, zero2;
    PACK2(accInit, Bv, 0.f);
    PACK2(zero2, 0.f, 0.f);
    float* __restrict__ aggp = g_agg[wr];

    for (int e0 = beg; e0 < end; e0 += EB) {
        int cnt = min(EB, end - e0);
#pragma unroll 4
        for (int k = 0; k < cnt; k++) {
            float2 a = g_sea[e0 + k];
            hs[w][k][lane] = fmaxf(fmaf(a.x, w10, fmaf(a.y, w11, b1v)), 0.f);
        }
        __syncwarp();
        for (int k = 0; k < cnt; k++) {
            int dst = g_sdst[e0 + k];
            const ulonglong2* __restrict__ hp =
                reinterpret_cast<const ulonglong2*>(hs[w][k]);
            ull a0 = accInit, a1 = zero2;
#pragma unroll
            for (int q = 0; q < 8; q++) {
                ulonglong2 h2 = hp[q];
                FMA2(a0, h2.x, G2[2 * q], a0);
                FMA2(a1, h2.y, G2[2 * q + 1], a1);
            }
            float l0, h0, l1, h1;
            UNPACK2(l0, h0, a0);
            UNPACK2(l1, h1, a1);
            atomicAdd(&aggp[dst * 32 + lane], (l0 + h0) + (l1 + h1));
        }
        __syncwarp();
    }
}

// ---------------------------------------------------------------------------
// kF: relu -> logits = x @ fc_w + fc_b -> log_softmax
// ---------------------------------------------------------------------------
__global__ __launch_bounds__(256) void kF(const float* __restrict__ fcw,
                                          const float* __restrict__ fcb,
                                          float* __restrict__ out, int rd) {
    int n = blockIdx.x * 256 + threadIdx.x;
    if (n >= NN) return;
    float l[NC];
#pragma unroll
    for (int c = 0; c < NC; c++) l[c] = fcb[c];
    const float4* xr = reinterpret_cast<const float4*>(g_agg[rd]) + n * 8;
#pragma unroll
    for (int q = 0; q < 8; q++) {
        float4 v = xr[q];
        float xv[4] = {fmaxf(v.x, 0.f), fmaxf(v.y, 0.f),
                       fmaxf(v.z, 0.f), fmaxf(v.w, 0.f)};
#pragma unroll
        for (int s = 0; s < 4; s++) {
            int o = q * 4 + s;
#pragma unroll
            for (int c = 0; c < NC; c++) l[c] = fmaf(xv[s], fcw[o * NC + c], l[c]);
        }
    }
    float m = l[0];
#pragma unroll
    for (int c = 1; c < NC; c++) m = fmaxf(m, l[c]);
    float s = 0.f;
#pragma unroll
    for (int c = 0; c < NC; c++) s += expf(l[c] - m);
    float lse = m + logf(s);
#pragma unroll
    for (int c = 0; c < NC; c++) out[n * NC + c] = l[c] - lse;
}

// ---------------------------------------------------------------------------
extern "C" void kernel_launch(void* const* d_in, const int* in_sizes, int n_in,
                              void* d_out, int out_size) {
    const float* x   = (const float*)d_in[0];   // [N, 4]
    const int*   ei  = (const int*)d_in[1];     // [2, E]
    const float* ea  = (const float*)d_in[2];   // [E, 2]
    const float *W1[3], *B1[3], *W2[3], *B2[3], *RT[3], *BI[3];
    for (int l = 0; l < 3; l++) {
        W1[l] = (const float*)d_in[3 + 6 * l + 0];
        B1[l] = (const float*)d_in[3 + 6 * l + 1];
        W2[l] = (const float*)d_in[3 + 6 * l + 2];
        B2[l] = (const float*)d_in[3 + 6 * l + 3];
        RT[l] = (const float*)d_in[3 + 6 * l + 4];
        BI[l] = (const float*)d_in[3 + 6 * l + 5];
    }
    const float* fcw = (const float*)d_in[21];
    const float* fcb = (const float*)d_in[22];
    float* out = (float*)d_out;

    const int gA = NN / 16;                     // 625 (exact)
    const int gB = NN / 8;                      // 1250 (one warp per node)
    const int gE = (NE + 255) / 256;            // 625
    const int gF = (NN + 255) / 256;
    const int gZ = (NN + 255) / 256;

    // ---- sort edges by src (once; shared by all layers) ----
    k_zero<<<gZ, 256>>>();
    k_hist<<<gE, 256>>>(ei);
    k_scan<<<1, 256>>>();
    k_scatter<<<gE, 256>>>(ei, ea);

    // ---- layer 0 (din=4, external input, write agg[0]) ----
    kAF<FIN, 0><<<gA, 256>>>(x, W2[0], B2[0], RT[0], BI[0], 0, 0);
    kB3<<<gB, 256>>>(W1[0], B1[0], 0);

    // ---- layer 1 (din=32, read agg[0] w/ relu, write agg[1]) ----
    kAF<HID, 1><<<gA, 256>>>(nullptr, W2[1], B2[1], RT[1], BI[1], 0, 1);
    kB3<<<gB, 256>>>(W1[1], B1[1], 1);

    // ---- layer 2 (din=32, read agg[1] w/ relu, write agg[0]) ----
    kAF<HID, 1><<<gA, 256>>>(nullptr, W2[2], B2[2], RT[2], BI[2], 1, 0);
    kB3<<<gB, 256>>>(W1[2], B1[2], 0);

    // ---- classifier + log_softmax (relu on read) ----
    kF<<<gF, 256>>>(fcw, fcb, out, 0);
}